// round 13
// baseline (speedup 1.0000x reference)
#include <cuda_runtime.h>
#include <cuda_fp16.h>
#include <cstdint>

#define N_TOK 4096
#define DIM   1024
#define HID   1024
#define NE    8
#define NSEG  9

// ---------------- scratch ---------------------------------------------------
__device__ int   g_cnt[NSEG];
__device__ int   g_assign_token[NE * N_TOK];
__device__ int   g_assign_slot [NE * N_TOK];
__device__ int   g_top_e[N_TOK * 2];
__device__ float g_top_w[N_TOK * 2];
__device__ __half g_Xf[(size_t)N_TOK * DIM];
// 27 matrices [k][n]: Wg[0..7], Wu[8..15], Wd[16..23], sg=24, su=25, sd=26
__device__ __half g_Wf[(size_t)27 * DIM * HID];
__device__ __half g_Hf[(size_t)NSEG * N_TOK * HID];
__device__ float g_rbuf[(size_t)3 * N_TOK * DIM];

// ---------------- helpers ---------------------------------------------------
__device__ __forceinline__ uint32_t smem_u32(const void* p) {
    uint32_t a;
    asm("{ .reg .u64 t; cvta.to.shared.u64 t, %1; cvt.u32.u64 %0, t; }"
        : "=r"(a) : "l"(p));
    return a;
}
#define CP_ASYNC16(dst, src) \
    asm volatile("cp.async.cg.shared.global [%0], [%1], 16;" :: "r"(dst), "l"(src))
#define CP_COMMIT() asm volatile("cp.async.commit_group;" ::: "memory")
#define CP_WAIT(n)  asm volatile("cp.async.wait_group %0;" :: "n"(n) : "memory")

__device__ __forceinline__ void ldsm_x4(uint32_t* r, uint32_t addr) {
    asm volatile("ldmatrix.sync.aligned.m8n8.x4.shared.b16 {%0,%1,%2,%3}, [%4];"
        : "=r"(r[0]), "=r"(r[1]), "=r"(r[2]), "=r"(r[3]) : "r"(addr));
}
__device__ __forceinline__ void ldsm_x2_t(uint32_t* r, uint32_t addr) {
    asm volatile("ldmatrix.sync.aligned.m8n8.x2.trans.shared.b16 {%0,%1}, [%2];"
        : "=r"(r[0]), "=r"(r[1]) : "r"(addr));
}
__device__ __forceinline__ void mma_f16(float* d, const uint32_t* a, const uint32_t* b) {
    asm volatile(
        "mma.sync.aligned.m16n8k16.row.col.f32.f16.f16.f32 "
        "{%0,%1,%2,%3}, {%4,%5,%6,%7}, {%8,%9}, {%0,%1,%2,%3};"
        : "+f"(d[0]), "+f"(d[1]), "+f"(d[2]), "+f"(d[3])
        : "r"(a[0]), "r"(a[1]), "r"(a[2]), "r"(a[3]), "r"(b[0]), "r"(b[1]));
}
__device__ __forceinline__ float silu(float g) { return g / (1.f + __expf(-g)); }

__device__ __forceinline__ void convert_one(const float* __restrict__ src,
                                            int m, size_t i4)
{
    float4 v = ((const float4*)src)[i4];
    __half2 a = __floats2half2_rn(v.x, v.y);
    __half2 b = __floats2half2_rn(v.z, v.w);
    size_t o = (size_t)m * (DIM * HID / 4) + i4;
    ((uint2*)g_Wf)[o] = make_uint2(*(uint32_t*)&a, *(uint32_t*)&b);
}

// ---------------- small kernels ---------------------------------------------
__global__ void zero_kernel() {
    int t = threadIdx.x;
    if (t < NE) g_cnt[t] = 0;
    if (t == NE) g_cnt[NE] = N_TOK;
}

__global__ void convert_x_kernel(const float* __restrict__ x) {
    size_t base = (size_t)blockIdx.x * 1024 + threadIdx.x;
    float4 v[4];
    #pragma unroll
    for (int j = 0; j < 4; j++) v[j] = ((const float4*)x)[base + j * 256];
    #pragma unroll
    for (int j = 0; j < 4; j++) {
        __half2 a = __floats2half2_rn(v[j].x, v[j].y);
        __half2 b = __floats2half2_rn(v[j].z, v[j].w);
        ((uint2*)g_Xf)[base + j * 256] = make_uint2(*(uint32_t*)&a, *(uint32_t*)&b);
    }
}

// chunk A: Wg[0..3], Wu[0..3], sg, su  (10 matrices)
__global__ void convert_w_guA_kernel(
    const float* __restrict__ Wg, const float* __restrict__ Wu,
    const float* __restrict__ sg, const float* __restrict__ su)
{
    int by = blockIdx.y;
    int m;
    const float* src;
    if      (by < 4) { src = Wg + (size_t)by * DIM * HID;       m = by; }
    else if (by < 8) { src = Wu + (size_t)(by - 4) * DIM * HID; m = 8 + (by - 4); }
    else if (by == 8){ src = sg;                                m = 24; }
    else             { src = su;                                m = 25; }
    size_t base = (size_t)blockIdx.x * 1024 + threadIdx.x;
    #pragma unroll
    for (int j = 0; j < 4; j++) convert_one(src, m, base + j * 256);
}

// chunk B: Wg[4..7], Wu[4..7]  (8 matrices)
__global__ void convert_w_guB_kernel(
    const float* __restrict__ Wg, const float* __restrict__ Wu)
{
    int by = blockIdx.y;
    int m;
    const float* src;
    if (by < 4) { src = Wg + (size_t)(4 + by) * DIM * HID;       m = 4 + by; }
    else        { src = Wu + (size_t)(by) * DIM * HID;           m = 8 + by; }
    size_t base = (size_t)blockIdx.x * 1024 + threadIdx.x;
    #pragma unroll
    for (int j = 0; j < 4; j++) convert_one(src, m, base + j * 256);
}

// down matrices (9): 16..23, 26
__global__ void convert_w_d_kernel(
    const float* __restrict__ Wd, const float* __restrict__ sd)
{
    int by = blockIdx.y;
    int m = (by < 8) ? 16 + by : 26;
    const float* src = (by < 8) ? Wd + (size_t)by * DIM * HID : sd;
    size_t base = (size_t)blockIdx.x * 1024 + threadIdx.x;
    #pragma unroll
    for (int j = 0; j < 4; j++) convert_one(src, m, base + j * 256);
}

// router: 1 token per warp, 512 blocks
__global__ __launch_bounds__(256, 4) void router_kernel(
    const float* __restrict__ X, const float* __restrict__ Wr,
    const float* __restrict__ loop_table, const int* __restrict__ loop_idx)
{
    __shared__ float4 sW[NE][256];
    __shared__ float s_bias[NE];
    const int tid = threadIdx.x, warp = tid >> 5, lane = tid & 31;

    for (int i = tid; i < NE * 256; i += 256) {
        int e = i >> 8, k4 = i & 255;
        sW[e][k4] = make_float4(Wr[(size_t)(k4 * 4 + 0) * NE + e],
                                Wr[(size_t)(k4 * 4 + 1) * NE + e],
                                Wr[(size_t)(k4 * 4 + 2) * NE + e],
                                Wr[(size_t)(k4 * 4 + 3) * NE + e]);
    }
    const float* le = loop_table + (size_t)loop_idx[0] * DIM;
    float b = 0.f;
    for (int d = lane; d < DIM; d += 32)
        b += le[d] * Wr[(size_t)(DIM + d) * NE + warp];
    #pragma unroll
    for (int o = 16; o; o >>= 1) b += __shfl_xor_sync(~0u, b, o);
    if (lane == 0) s_bias[warp] = b;
    __syncthreads();

    const int t = blockIdx.x * 8 + warp;
    const float4* xr = (const float4*)(X + (size_t)t * DIM);
    float acc[NE];
    #pragma unroll
    for (int e = 0; e < NE; e++) acc[e] = 0.f;
    #pragma unroll 1
    for (int i = 0; i < 8; i++) {
        float4 xv = xr[lane + 32 * i];
        const float4* swp = &sW[0][lane + 32 * i];
        #pragma unroll
        for (int e = 0; e < NE; e++) {
            float4 w = swp[e * 256];
            acc[e] += xv.x * w.x + xv.y * w.y + xv.z * w.z + xv.w * w.w;
        }
    }
    #pragma unroll
    for (int e = 0; e < NE; e++)
        #pragma unroll
        for (int o = 16; o; o >>= 1) acc[e] += __shfl_xor_sync(~0u, acc[e], o);

    if (lane == 0) {
        float p[NE];
        #pragma unroll
        for (int e = 0; e < NE; e++)
            p[e] = 1.f / (1.f + expf(-(acc[e] + s_bias[e])));
        int i0 = 0; float v0 = p[0];
        #pragma unroll
        for (int e = 1; e < NE; e++) if (p[e] > v0) { v0 = p[e]; i0 = e; }
        int i1 = -1; float v1 = -1e30f;
        #pragma unroll
        for (int e = 0; e < NE; e++) {
            if (e == i0) continue;
            if (p[e] > v1) { v1 = p[e]; i1 = e; }
        }
        g_top_e[t * 2 + 0] = i0;  g_top_e[t * 2 + 1] = i1;
        g_top_w[t * 2 + 0] = v0;  g_top_w[t * 2 + 1] = v1;
    }
}

__global__ void dispatch_kernel() {
    int t = blockIdx.x * blockDim.x + threadIdx.x;
    if (t >= N_TOK) return;
    #pragma unroll
    for (int k = 0; k < 2; k++) {
        int e = g_top_e[t * 2 + k];
        int pos = atomicAdd(&g_cnt[e], 1);
        g_assign_token[e * N_TOK + pos] = t;
        g_assign_slot [e * N_TOK + pos] = k;
    }
}

// ---------------- GEMM1: X @ {Wg,Wu}[e], fused SiLU -> fp16 h ---------------
// Block 128m x 64n, BK=64 per stage (16 stages), 3-stage ring.
// A pitch 144B (128B data + 16 pad), B pitch 144B.
#define S1_A  0u
#define S1_G  18432u
#define S1_U  27648u
#define S1_STG 36864u

__global__ __launch_bounds__(256) void gemm1_kernel(int part) {
    extern __shared__ char sm[];
    __shared__ int s_token[128];

    // part 0: blockIdx.z 0..4 -> segs {0,1,2,3,8}; part 1: z 0..3 -> segs 4..7
    const int e = (part == 0) ? ((blockIdx.z == 4) ? 8 : blockIdx.z)
                              : (4 + blockIdx.z);
    const int cnt = g_cnt[e];
    const int m0  = blockIdx.y * 128;
    if (m0 >= cnt) return;
    const int n0  = blockIdx.x * 64;
    const int tid = threadIdx.x, wid = tid >> 5, lane = tid & 31;

    const int ig = (e < NE) ? e : 24;
    const int iu = (e < NE) ? 8 + e : 25;

    if (tid < 128) {
        int r = m0 + tid;
        s_token[tid] = (e < NE) ? ((r < cnt) ? g_assign_token[e * N_TOK + r] : 0) : r;
    }
    __syncthreads();
    const uint32_t sb = smem_u32(sm);

    const char* wg = (const char*)(g_Wf + (size_t)ig * DIM * HID);
    const char* wu = (const char*)(g_Wf + (size_t)iu * DIM * HID);

    // loaders: A 4/thread, G 2/thread, U 2/thread
    const int arow = tid >> 1, apart = (tid & 1) * 16;
    const char* aSrc = (const char*)(g_Xf + (size_t)s_token[arow] * DIM) + apart;
    const uint32_t aDst = sb + S1_A + arow * 144 + apart;
    const int brow = tid >> 2, bpart = (tid & 3) * 16;
    const char* gSrc = wg + (size_t)brow * HID * 2 + n0 * 2 + bpart;
    const char* uSrc = wu + (size_t)brow * HID * 2 + n0 * 2 + bpart;
    const uint32_t gDst = sb + S1_G + brow * 144 + bpart;
    const uint32_t uDst = sb + S1_U + brow * 144 + bpart;

#define G_LOAD(k0, buf) do { \
        uint32_t _o = (uint32_t)(buf) * S1_STG; \
        size_t _ab = (size_t)(k0) * 2; \
        size_t _bb = (size_t)(k0) * HID * 2; \
        _Pragma("unroll") for (int _j = 0; _j < 4; _j++) \
            CP_ASYNC16(aDst + _o + _j * 32, aSrc + _ab + _j * 32); \
        _Pragma("unroll") for (int _j = 0; _j < 2; _j++) { \
            CP_ASYNC16(gDst + _o + _j * 64, gSrc + _bb + _j * 64); \
            CP_ASYNC16(uDst + _o + _j * 64, uSrc + _bb + _j * 64); \
        } \
        CP_COMMIT(); } while (0)

    const int wm = (wid & 3) * 32, wn = (wid >> 2) * 32;
    const int am = (lane & 7) + ((lane >> 3) & 1) * 8;
    const uint32_t ako = (lane >> 4) * 16;
    const uint32_t aB = sb + S1_A + (wm + am) * 144 + ako;
    const int bk = lane & 15;
    const uint32_t bG = sb + S1_G + bk * 144 + wn * 2;
    const uint32_t bU = sb + S1_U + bk * 144 + wn * 2;

    float accG[2][4][4], accU[2][4][4];
    #pragma unroll
    for (int i = 0; i < 2; i++)
        #pragma unroll
        for (int j = 0; j < 4; j++)
            #pragma unroll
            for (int q = 0; q < 4; q++) { accG[i][j][q] = 0.f; accU[i][j][q] = 0.f; }

    G_LOAD(0, 0);
    G_LOAD(64, 1);
    CP_WAIT(1); __syncthreads();

    int cur = 0;
    for (int s = 0; s < 16; s++) {
        int ldb = cur + 2; if (ldb >= 3) ldb -= 3;
        if (s + 2 < 16) G_LOAD((s + 2) * 64, ldb);

        const uint32_t off = (uint32_t)cur * S1_STG;
        #pragma unroll
        for (int ks = 0; ks < 4; ks++) {
            uint32_t a[2][4], bg[4][2], bu[4][2];
            #pragma unroll
            for (int i = 0; i < 2; i++)
                ldsm_x4(a[i], aB + off + ks * 32 + i * 2304);
            #pragma unroll
            for (int j = 0; j < 4; j++) {
                ldsm_x2_t(bg[j], bG + off + ks * 2304 + j * 16);
                ldsm_x2_t(bu[j], bU + off + ks * 2304 + j * 16);
            }
            #pragma unroll
            for (int i = 0; i < 2; i++)
                #pragma unroll
                for (int j = 0; j < 4; j++) {
                    mma_f16(accG[i][j], a[i], bg[j]);
                    mma_f16(accU[i][j], a[i], bu[j]);
                }
        }
        if (s + 2 < 16) CP_WAIT(1); else CP_WAIT(0);
        __syncthreads();
        cur++; if (cur == 3) cur = 0;
    }

    const int qr = lane >> 2, r4 = lane & 3;
    #pragma unroll
    for (int i = 0; i < 2; i++) {
        const int lr0 = wm + i * 16 + qr, lr1 = lr0 + 8;
        const bool ok0 = (m0 + lr0) < cnt, ok1 = (m0 + lr1) < cnt;
        __half* d0 = g_Hf + ((size_t)e * N_TOK + m0 + lr0) * HID + n0;
        __half* d1 = g_Hf + ((size_t)e * N_TOK + m0 + lr1) * HID + n0;
        #pragma unroll
        for (int j = 0; j < 4; j++) {
            const int col = wn + j * 8 + r4 * 2;
            float h00 = silu(accG[i][j][0]) * accU[i][j][0];
            float h01 = silu(accG[i][j][1]) * accU[i][j][1];
            float h10 = silu(accG[i][j][2]) * accU[i][j][2];
            float h11 = silu(accG[i][j][3]) * accU[i][j][3];
            if (ok0) *(__half2*)(d0 + col) = __floats2half2_rn(h00, h01);
            if (ok1) *(__half2*)(d1 + col) = __floats2half2_rn(h10, h11);
        }
    }
#undef G_LOAD
}

// ---------------- GEMM2: h @ Wd[e] -> scattered fp32 rbuf -------------------
// Block 128m x 64n, BK=64 per stage (16 stages), 3-stage ring.
#define S2_A  0u
#define S2_B  18432u
#define S2_STG 27648u

__global__ __launch_bounds__(256) void gemm2_kernel() {
    extern __shared__ char sm[];
    __shared__ int s_dst[128];

    const int e   = blockIdx.z;
    const int cnt = g_cnt[e];
    const int m0  = blockIdx.y * 128;
    if (m0 >= cnt) return;
    const int n0  = blockIdx.x * 64;
    const int tid = threadIdx.x, wid = tid >> 5, lane = tid & 31;

    const int id = (e < NE) ? 16 + e : 26;

    if (tid < 128) {
        int r = m0 + tid, dst = 0;
        if (r < cnt) {
            if (e < NE)
                dst = g_assign_slot[e * N_TOK + r] * N_TOK + g_assign_token[e * N_TOK + r];
            else
                dst = 2 * N_TOK + r;
        }
        s_dst[tid] = dst;
    }
    __syncthreads();
    const uint32_t sb = smem_u32(sm);

    const char* wd = (const char*)(g_Wf + (size_t)id * DIM * HID);

    const int arow = tid >> 1, apart = (tid & 1) * 16;
    const char* aSrc = (const char*)(g_Hf + ((size_t)e * N_TOK + m0 + arow) * HID) + apart;
    const uint32_t aDst = sb + S2_A + arow * 144 + apart;
    const int brow = tid >> 2, bpart = (tid & 3) * 16;
    const char* bSrc = wd + (size_t)brow * DIM * 2 + n0 * 2 + bpart;
    const uint32_t bDst = sb + S2_B + brow * 144 + bpart;

#define G_LOAD(k0, buf) do { \
        uint32_t _o = (uint32_t)(buf) * S2_STG; \
        size_t _ab = (size_t)(k0) * 2; \
        size_t _bb = (size_t)(k0) * DIM * 2; \
        _Pragma("unroll") for (int _j = 0; _j < 4; _j++) \
            CP_ASYNC16(aDst + _o + _j * 32, aSrc + _ab + _j * 32); \
        _Pragma("unroll") for (int _j = 0; _j < 2; _j++) \
            CP_ASYNC16(bDst + _o + _j * 64, bSrc + _bb + _j * 64); \
        CP_COMMIT(); } while (0)

    const int wm = (wid & 3) * 32, wn = (wid >> 2) * 32;
    const int am = (lane & 7) + ((lane >> 3) & 1) * 8;
    const uint32_t ako = (lane >> 4) * 16;
    const uint32_t aB = sb + S2_A + (wm + am) * 144 + ako;
    const int bk = lane & 15;
    const uint32_t bB = sb + S2_B + bk * 144 + wn * 2;

    float acc[2][4][4];
    #pragma unroll
    for (int i = 0; i < 2; i++)
        #pragma unroll
        for (int j = 0; j < 4; j++)
            #pragma unroll
            for (int q = 0; q < 4; q++) acc[i][j][q] = 0.f;

    G_LOAD(0, 0);
    G_LOAD(64, 1);
    CP_WAIT(1); __syncthreads();

    int cur = 0;
    for (int s = 0; s < 16; s++) {
        int ldb = cur + 2; if (ldb >= 3) ldb -= 3;
        if (s + 2 < 16) G_LOAD((s + 2) * 64, ldb);

        const uint32_t off = (uint32_t)cur * S2_STG;
        #pragma unroll
        for (int ks = 0; ks < 4; ks++) {
            uint32_t a[2][4], b[4][2];
            #pragma unroll
            for (int i = 0; i < 2; i++)
                ldsm_x4(a[i], aB + off + ks * 32 + i * 2304);
            #pragma unroll
            for (int j = 0; j < 4; j++)
                ldsm_x2_t(b[j], bB + off + ks * 2304 + j * 16);
            #pragma unroll
            for (int i = 0; i < 2; i++)
                #pragma unroll
                for (int j = 0; j < 4; j++)
                    mma_f16(acc[i][j], a[i], b[j]);
        }
        if (s + 2 < 16) CP_WAIT(1); else CP_WAIT(0);
        __syncthreads();
        cur++; if (cur == 3) cur = 0;
    }

    const int qr = lane >> 2, r4 = lane & 3;
    #pragma unroll
    for (int i = 0; i < 2; i++) {
        const int lr0 = wm + i * 16 + qr, lr1 = lr0 + 8;
        const bool ok0 = (m0 + lr0) < cnt, ok1 = (m0 + lr1) < cnt;
        float* d0 = g_rbuf + (size_t)s_dst[lr0] * DIM + n0;
        float* d1 = g_rbuf + (size_t)s_dst[lr1] * DIM + n0;
        #pragma unroll
        for (int j = 0; j < 4; j++) {
            const int col = wn + j * 8 + r4 * 2;
            if (ok0) *(float2*)(d0 + col) = make_float2(acc[i][j][0], acc[i][j][1]);
            if (ok1) *(float2*)(d1 + col) = make_float2(acc[i][j][2], acc[i][j][3]);
        }
    }
#undef G_LOAD
}

// ---------------- combine ---------------------------------------------------
__global__ void combine_kernel(float* __restrict__ out) {
    int i4 = blockIdx.x * 256 + threadIdx.x;
    int t  = i4 >> 8;
    float w0 = g_top_w[2 * t], w1 = g_top_w[2 * t + 1];
    float4 a = ((const float4*)g_rbuf)[i4];
    float4 b = ((const float4*)g_rbuf)[(size_t)(N_TOK * DIM / 4) + i4];
    float4 c = ((const float4*)g_rbuf)[(size_t)(2 * N_TOK * DIM / 4) + i4];
    float4 o;
    o.x = c.x + w0 * a.x + w1 * b.x;
    o.y = c.y + w0 * a.y + w1 * b.y;
    o.z = c.z + w0 * a.z + w1 * b.z;
    o.w = c.w + w0 * a.w + w1 * b.w;
    ((float4*)out)[i4] = o;
}

// ---------------- launch ----------------------------------------------------
extern "C" void kernel_launch(void* const* d_in, const int* in_sizes, int n_in,
                              void* d_out, int out_size)
{
    const float* x  = (const float*)d_in[0];
    const float* sg = (const float*)d_in[1];
    const float* su = (const float*)d_in[2];
    const float* sd = (const float*)d_in[3];
    const float* Wg = (const float*)d_in[4];
    const float* Wu = (const float*)d_in[5];
    const float* Wd = (const float*)d_in[6];
    const float* Wr = (const float*)d_in[7];
    const float* lt = (const float*)d_in[8];
    const int*   li = (const int*)d_in[9];
    float* out = (float*)d_out;
    (void)in_sizes; (void)n_in; (void)out_size;

    static cudaStream_t s2 = nullptr;
    static cudaEvent_t evFork = nullptr, evA = nullptr, evB = nullptr, evD = nullptr;
    static int init_done = 0;
    if (!init_done) {
        cudaFuncSetAttribute(gemm1_kernel, cudaFuncAttributeMaxDynamicSharedMemorySize, 3 * S1_STG);
        cudaFuncSetAttribute(gemm2_kernel, cudaFuncAttributeMaxDynamicSharedMemorySize, 3 * S2_STG);
        cudaStreamCreateWithFlags(&s2, cudaStreamNonBlocking);
        cudaEventCreateWithFlags(&evFork, cudaEventDisableTiming);
        cudaEventCreateWithFlags(&evA, cudaEventDisableTiming);
        cudaEventCreateWithFlags(&evB, cudaEventDisableTiming);
        cudaEventCreateWithFlags(&evD, cudaEventDisableTiming);
        init_done = 1;
    }

    cudaEventRecord(evFork, 0);
    cudaStreamWaitEvent(s2, evFork, 0);

    zero_kernel<<<1, 32>>>();
    router_kernel<<<N_TOK / 8, 256>>>(x, Wr, lt, li);
    dispatch_kernel<<<N_TOK / 256, 256>>>();

    convert_x_kernel<<<(N_TOK * DIM / 4) / 1024, 256, 0, s2>>>(x);
    convert_w_guA_kernel<<<dim3((DIM * HID / 4) / 1024, 10), 256, 0, s2>>>(Wg, Wu, sg, su);
    cudaEventRecord(evA, s2);
    convert_w_guB_kernel<<<dim3((DIM * HID / 4) / 1024, 8), 256, 0, s2>>>(Wg, Wu);
    cudaEventRecord(evB, s2);
    convert_w_d_kernel<<<dim3((DIM * HID / 4) / 1024, 9), 256, 0, s2>>>(Wd, sd);
    cudaEventRecord(evD, s2);

    cudaStreamWaitEvent(0, evA, 0);
    gemm1_kernel<<<dim3(16, 32, 5), 256, 3 * S1_STG>>>(0);   // experts 0-3 + shared
    cudaStreamWaitEvent(0, evB, 0);
    gemm1_kernel<<<dim3(16, 32, 4), 256, 3 * S1_STG>>>(1);   // experts 4-7
    cudaStreamWaitEvent(0, evD, 0);
    gemm2_kernel<<<dim3(16, 32, NSEG), 256, 3 * S2_STG>>>();
    combine_kernel<<<(N_TOK * (DIM / 4)) / 256, 256>>>(out);
}